// round 1
// baseline (speedup 1.0000x reference)
#include <cuda_runtime.h>
#include <cstdint>

// Problem shape (fixed by the dataset): B=512, S=1024, T=64
#define Bn 512
#define Sn 1024
#define Tn 64

typedef unsigned long long u64;

// Scratch (allocation-free rule: device globals)
__device__ float g_z[Bn];
__device__ float g_sc[Bn];

__device__ __forceinline__ u64 ffma2(u64 a, u64 b, u64 c) {
    u64 d;
    asm("fma.rn.f32x2 %0, %1, %2, %3;" : "=l"(d) : "l"(a), "l"(b), "l"(c));
    return d;
}
__device__ __forceinline__ u64 pk2(float a, float b) {
    u64 d;
    asm("mov.b64 %0, {%1,%2};" : "=l"(d) : "f"(a), "f"(b));
    return d;
}
__device__ __forceinline__ float2 upk(u64 p) {
    float2 r;
    asm("mov.b64 {%0,%1}, %2;" : "=f"(r.x), "=f"(r.y) : "l"(p));
    return r;
}

// ---------------------------------------------------------------------------
// Kernel 1: forward recursion (partition function) — one 64-thread block per
// batch element. Thread j owns dp[j]. Inner T×T contraction done in the
// linear domain with E = exp(trans) held as f32x2 pairs in registers, v
// broadcast from shared memory as 64-bit loads, accumulated with FFMA2.
// ---------------------------------------------------------------------------
__global__ __launch_bounds__(64) void crf_forward(
    const float* __restrict__ em,    // [B, S, T]
    const float* __restrict__ mask,  // [B, S]
    const float* __restrict__ tr)    // [T, T]
{
    const int b    = blockIdx.x;
    const int j    = threadIdx.x;   // 0..63 = tag column
    const int wid  = j >> 5;
    const int lane = j & 31;

    __shared__ __align__(16) float vbuf[2][Tn];  // double-buffered exp(dp - M)
    __shared__ float mrow[Sn];                   // mask row for this batch
    __shared__ float wm[2];                      // per-warp running max (stabilizer)
    __shared__ float fin[4];                     // final logsumexp scratch

    // Stage mask row into smem (read once per step as broadcast)
    for (int i = j; i < Sn; i += 64) mrow[i] = mask[b * Sn + i];

    // E columns in registers: Ereg[k] = (exp(tr[2k][j]), exp(tr[2k+1][j]))
    u64 Ereg[32];
#pragma unroll
    for (int k = 0; k < 32; k++) {
        float a = __expf(tr[(2 * k) * Tn + j]);
        float c = __expf(tr[(2 * k + 1) * Tn + j]);
        Ereg[k] = pk2(a, c);
    }

    // Emission stream for this thread's column, prefetched 8 steps ahead
    const float* ep = em + (size_t)b * Sn * Tn + j;
    float ebuf[8];
#pragma unroll
    for (int d = 0; d < 8; d++) ebuf[d] = __ldg(ep + d * Tn);

    float dp = 0.0f;   // dp[j]
    float M  = 0.0f;   // block-wide stabilizer (stale max of dp)
    __syncthreads();   // mrow visible before first use

    for (int tb = 0; tb < Sn; tb += 8) {
#pragma unroll
        for (int u = 0; u < 8; u++) {
            const int t   = tb + u;
            const int par = u & 1;

            // publish v[j] = exp(dp[j] - M)
            vbuf[par][j] = __expf(dp - M);
            __syncthreads();

            // acc[j] = sum_i v[i] * E[i][j]   (32 FFMA2, 4 chains for ILP)
            const u64* v2 = (const u64*)(&vbuf[par][0]);
            u64 a0 = 0ull, a1 = 0ull, a2 = 0ull, a3 = 0ull;
#pragma unroll
            for (int k = 0; k < 32; k += 4) {
                a0 = ffma2(v2[k + 0], Ereg[k + 0], a0);
                a1 = ffma2(v2[k + 1], Ereg[k + 1], a1);
                a2 = ffma2(v2[k + 2], Ereg[k + 2], a2);
                a3 = ffma2(v2[k + 3], Ereg[k + 3], a3);
            }
            float2 f0 = upk(a0), f1 = upk(a1), f2 = upk(a2), f3 = upk(a3);
            float ssum = ((f0.x + f0.y) + (f1.x + f1.y)) +
                         ((f2.x + f2.y) + (f3.x + f3.y));

            // consume staged emission, prefetch t+8
            float e = ebuf[u];
            if (t + 8 < Sn) ebuf[u] = __ldg(ep + (size_t)(t + 8) * Tn);

            float mt  = mrow[t];
            float dpn = e + M + __logf(ssum);
            dp = fmaf(mt, dpn - dp, dp);   // mask blend: m*dpn + (1-m)*dp

            // Stabilizer refresh: produce at t%4==0, consume at end of t%4==1
            // (the step-(t+1) __syncthreads orders the STS before the read).
            if ((u & 3) == 0) {
                float w = dp;
#pragma unroll
                for (int o = 16; o; o >>= 1)
                    w = fmaxf(w, __shfl_xor_sync(0xffffffffu, w, o));
                if (lane == 0) wm[wid] = w;
            } else if ((u & 3) == 1) {
                M = fmaxf(wm[0], wm[1]);
            }
        }
    }

    // z[b] = logsumexp_j dp[j]
    float w = dp;
#pragma unroll
    for (int o = 16; o; o >>= 1)
        w = fmaxf(w, __shfl_xor_sync(0xffffffffu, w, o));
    if (lane == 0) fin[wid] = w;
    __syncthreads();
    float gm = fmaxf(fin[0], fin[1]);
    float ex = __expf(dp - gm);
#pragma unroll
    for (int o = 16; o; o >>= 1)
        ex += __shfl_xor_sync(0xffffffffu, ex, o);
    if (lane == 0) fin[2 + wid] = ex;
    __syncthreads();
    if (j == 0) g_z[b] = gm + logf(fin[2] + fin[3]);
}

// ---------------------------------------------------------------------------
// Kernel 2: gold path scores. One block per batch, threads stride over time.
// ---------------------------------------------------------------------------
__global__ __launch_bounds__(256) void crf_gold(
    const float* __restrict__ em,
    const int*   __restrict__ tags,
    const float* __restrict__ mask,
    const float* __restrict__ tr)
{
    __shared__ float red[256];
    const int b   = blockIdx.x;
    const int tid = threadIdx.x;

    const int* tg = tags + b * Sn;
    float acc = 0.0f;
    for (int s = 1 + tid; s < Sn; s += 256) {
        int   t1  = tg[s];
        int   t0  = tg[s - 1];
        float mt  = mask[b * Sn + s];
        float emv = __ldg(em + (size_t)b * Sn * Tn + (size_t)s * Tn + t1);
        float trv = tr[t0 * Tn + t1];
        acc += (emv + trv) * mt;
    }
    red[tid] = acc;
    __syncthreads();
    for (int st = 128; st; st >>= 1) {
        if (tid < st) red[tid] += red[tid + st];
        __syncthreads();
    }
    if (tid == 0) g_sc[b] = red[0];
}

// ---------------------------------------------------------------------------
// Kernel 3: out = -mean(z - score)  (deterministic tree reduction)
// ---------------------------------------------------------------------------
__global__ __launch_bounds__(Bn) void crf_final(float* __restrict__ out)
{
    __shared__ float red[Bn];
    const int tid = threadIdx.x;
    red[tid] = g_z[tid] - g_sc[tid];
    __syncthreads();
    for (int st = Bn / 2; st; st >>= 1) {
        if (tid < st) red[tid] += red[tid + st];
        __syncthreads();
    }
    if (tid == 0) out[0] = -red[0] / (float)Bn;
}

extern "C" void kernel_launch(void* const* d_in, const int* in_sizes, int n_in,
                              void* d_out, int out_size)
{
    const float* em   = (const float*)d_in[0];  // emissions [B,S,T] f32
    const int*   tags = (const int*)  d_in[1];  // tags [B,S] i32
    const float* mask = (const float*)d_in[2];  // mask [B,S] f32
    const float* tr   = (const float*)d_in[3];  // transitions [T,T] f32

    crf_forward<<<Bn, 64>>>(em, mask, tr);
    crf_gold<<<Bn, 256>>>(em, tags, mask, tr);
    crf_final<<<1, Bn>>>((float*)d_out);
}

// round 2
// speedup vs baseline: 1.2354x; 1.2354x over previous
#include <cuda_runtime.h>
#include <cstdint>

// Problem shape (fixed by the dataset): B=512, S=1024, T=64
#define Bn 512
#define Sn 1024
#define Tn 64

typedef unsigned long long u64;

// Scratch (allocation-free rule: device globals)
__device__ float g_z[Bn];
__device__ float g_sc[Bn];

__device__ __forceinline__ u64 ffma2(u64 a, u64 b, u64 c) {
    u64 d;
    asm("fma.rn.f32x2 %0, %1, %2, %3;" : "=l"(d) : "l"(a), "l"(b), "l"(c));
    return d;
}
__device__ __forceinline__ u64 fadd2(u64 a, u64 b) {
    u64 d;
    asm("add.rn.f32x2 %0, %1, %2;" : "=l"(d) : "l"(a), "l"(b));
    return d;
}
__device__ __forceinline__ u64 pk2(float a, float b) {
    u64 d;
    asm("mov.b64 %0, {%1,%2};" : "=l"(d) : "f"(a), "f"(b));
    return d;
}
__device__ __forceinline__ float2 upk(u64 p) {
    float2 r;
    asm("mov.b64 {%0,%1}, %2;" : "=f"(r.x), "=f"(r.y) : "l"(p));
    return r;
}

// ---------------------------------------------------------------------------
// Kernel 1: forward recursion in the LINEAR domain.
//   s_{t+1}[j] = (sum_i s_t[i] * E[i][j]) * exp(e_t[j]),  E = exp(trans)
//   dp_t[j] = log(s_t[j]) + offk*ln2  (offk tracked via power-of-2 renorm)
// One 64-thread block (2 warps) per batch element; thread j owns column j.
// No exp/log on the recursion critical path; renorm every 8 steps uses the
// exponent bits of s[0] (already loaded by every thread, uniform).
// ---------------------------------------------------------------------------
__global__ __launch_bounds__(64) void crf_forward(
    const float* __restrict__ em,    // [B, S, T]
    const float* __restrict__ mask,  // [B, S]
    const float* __restrict__ tr)    // [T, T]
{
    const int b    = blockIdx.x;
    const int j    = threadIdx.x;   // tag column
    const int wid  = j >> 5;
    const int lane = j & 31;

    __shared__ __align__(16) float sbuf[2][Tn];  // double-buffered s vector
    __shared__ float2 mrow[Sn];                  // (m, 1-m) per step
    __shared__ float fin[4];

    // Stage mask row as (m, 1-m) pairs
    for (int i = j; i < Sn; i += 64) {
        float m = mask[b * Sn + i];
        mrow[i] = make_float2(m, 1.0f - m);
    }

    // E columns in registers: Ereg[k] = (exp(tr[2k][j]), exp(tr[2k+1][j]))
    u64 Ereg[32];
#pragma unroll
    for (int k = 0; k < 32; k++) {
        float a = __expf(tr[(2 * k) * Tn + j]);
        float c = __expf(tr[(2 * k + 1) * Tn + j]);
        Ereg[k] = pk2(a, c);
    }

    // Raw emission stream for this column, prefetched 8 steps ahead.
    const float* ep = em + (size_t)b * Sn * Tn + j;
    float ebuf[8];
#pragma unroll
    for (int d = 0; d < 8; d++) ebuf[d] = __ldg(ep + d * Tn);

    float s    = 1.0f;   // s[j] = exp(dp[j] - offk*ln2)
    int   offk = 0;      // power-of-2 renormalization count
    __syncthreads();     // mrow visible

    for (int tb = 0; tb < Sn; tb += 8) {
#pragma unroll
        for (int u = 0; u < 8; u++) {
            const int t   = tb + u;
            const int par = u & 1;

            // exp of the staged (long-ready) emission — off the s-chain
            float f = __expf(ebuf[u]);
            // refill prefetch slot for t+8
            if (t + 8 < Sn) ebuf[u] = __ldg(ep + (size_t)(t + 8) * Tn);

            // publish s[j]
            sbuf[par][j] = s;
            __syncthreads();

            // q[j] = sum_i s[i] * E[i][j]  — 16 broadcast LDS.128, 32 FFMA2
            const float4* v4 = (const float4*)(&sbuf[par][0]);
            float4 x0 = v4[0];
            u64 a0 = 0ull, a1 = 0ull, a2 = 0ull, a3 = 0ull;
            a0 = ffma2(pk2(x0.x, x0.y), Ereg[0], a0);
            a0 = ffma2(pk2(x0.z, x0.w), Ereg[1], a0);
#pragma unroll
            for (int k = 1; k < 16; k += 4) {
                float4 y0 = v4[k + 0];
                float4 y1 = v4[k + 1];
                float4 y2 = v4[k + 2];
                a1 = ffma2(pk2(y0.x, y0.y), Ereg[2 * k + 0], a1);
                a1 = ffma2(pk2(y0.z, y0.w), Ereg[2 * k + 1], a1);
                a2 = ffma2(pk2(y1.x, y1.y), Ereg[2 * k + 2], a2);
                a2 = ffma2(pk2(y1.z, y1.w), Ereg[2 * k + 3], a2);
                a3 = ffma2(pk2(y2.x, y2.y), Ereg[2 * k + 4], a3);
                a3 = ffma2(pk2(y2.z, y2.w), Ereg[2 * k + 5], a3);
                if (k + 3 < 16) {
                    float4 y3 = v4[k + 3];
                    a0 = ffma2(pk2(y3.x, y3.y), Ereg[2 * k + 6], a0);
                    a0 = ffma2(pk2(y3.z, y3.w), Ereg[2 * k + 7], a0);
                }
            }
            u64 aa = fadd2(fadd2(a0, a1), fadd2(a2, a3));
            float2 p = upk(aa);
            float q = p.x + p.y;

            // masked update: s = m * q * f + (1-m) * s
            float2 mm = mrow[t];
            float oms = mm.y * s;          // off-chain (s from prev step)
            s = fmaf(mm.x, q * f, oms);

            // renorm every 8 steps by 2^-k, k from exponent of s[0]
            if (u == 7) {
                int ke = ((__float_as_int(x0.x) >> 23) & 0xff) - 127;
                offk += ke;
                s *= __int_as_float((127 - ke) << 23);
            }
        }
    }

    // z[b] = offk*ln2 + log(sum_j s[j])
    float x = s;
#pragma unroll
    for (int o = 16; o; o >>= 1)
        x += __shfl_xor_sync(0xffffffffu, x, o);
    if (lane == 0) fin[wid] = x;
    __syncthreads();
    if (j == 0) {
        double z = (double)offk * 0.6931471805599453
                 + (double)logf(fin[0] + fin[1]);
        g_z[b] = (float)z;
    }
}

// ---------------------------------------------------------------------------
// Kernel 2: gold path scores. One block per batch, threads stride over time.
// ---------------------------------------------------------------------------
__global__ __launch_bounds__(256) void crf_gold(
    const float* __restrict__ em,
    const int*   __restrict__ tags,
    const float* __restrict__ mask,
    const float* __restrict__ tr)
{
    __shared__ float red[256];
    const int b   = blockIdx.x;
    const int tid = threadIdx.x;

    const int* tg = tags + b * Sn;
    float acc = 0.0f;
    for (int s = 1 + tid; s < Sn; s += 256) {
        int   t1  = tg[s];
        int   t0  = tg[s - 1];
        float mt  = mask[b * Sn + s];
        float emv = __ldg(em + (size_t)b * Sn * Tn + (size_t)s * Tn + t1);
        float trv = tr[t0 * Tn + t1];
        acc += (emv + trv) * mt;
    }
    red[tid] = acc;
    __syncthreads();
    for (int st = 128; st; st >>= 1) {
        if (tid < st) red[tid] += red[tid + st];
        __syncthreads();
    }
    if (tid == 0) g_sc[b] = red[0];
}

// ---------------------------------------------------------------------------
// Kernel 3: out = -mean(z - score)
// ---------------------------------------------------------------------------
__global__ __launch_bounds__(Bn) void crf_final(float* __restrict__ out)
{
    __shared__ float red[Bn];
    const int tid = threadIdx.x;
    red[tid] = g_z[tid] - g_sc[tid];
    __syncthreads();
    for (int st = Bn / 2; st; st >>= 1) {
        if (tid < st) red[tid] += red[tid + st];
        __syncthreads();
    }
    if (tid == 0) out[0] = -red[0] / (float)Bn;
}

extern "C" void kernel_launch(void* const* d_in, const int* in_sizes, int n_in,
                              void* d_out, int out_size)
{
    const float* em   = (const float*)d_in[0];  // emissions [B,S,T] f32
    const int*   tags = (const int*)  d_in[1];  // tags [B,S] i32
    const float* mask = (const float*)d_in[2];  // mask [B,S] f32
    const float* tr   = (const float*)d_in[3];  // transitions [T,T] f32

    crf_forward<<<Bn, 64>>>(em, mask, tr);
    crf_gold<<<Bn, 256>>>(em, tags, mask, tr);
    crf_final<<<1, Bn>>>((float*)d_out);
}